// round 1
// baseline (speedup 1.0000x reference)
#include <cuda_runtime.h>

#define T_  16384
#define NB  64
#define CIN 8
#define NH  32
#define NE  64

// Scratch (device globals; allocation-free contract).
// Time-major layouts: u1[t][b*32+h], u2[t][b*64+e]. Padded by 64 rows so the
// double-buffered prefetch in the LIF kernels may harmlessly over-read.
__device__ float    g_u1[(size_t)(T_ + 64) * (NB * NH)];
__device__ float    g_u2[(size_t)(T_ + 64) * (NB * NE)];
__device__ unsigned g_mask[(size_t)NB * T_];   // spike bitmask per (b,t), bit = channel h

// ---------------------------------------------------------------------------
// K1: conv1 (k=3, same) + BN1 -> g_u1 in [t][b*32+h] layout.
// Warp = 32 h-channels of one batch; lanes share x columns (broadcast loads).
// ---------------------------------------------------------------------------
__global__ void __launch_bounds__(256) k1_conv1(
    const float* __restrict__ x,  const float* __restrict__ w1,
    const float* __restrict__ b1, const float* __restrict__ g1,
    const float* __restrict__ be1,const float* __restrict__ m1,
    const float* __restrict__ v1)
{
    const int warp = threadIdx.x >> 5;
    const int lane = threadIdx.x & 31;
    const int b    = blockIdx.y;
    const int tb   = (blockIdx.x * 8 + warp) * 128;   // 128 timesteps per warp
    const int h    = lane;

    float wk0[CIN], wk1[CIN], wk2[CIN];
#pragma unroll
    for (int c = 0; c < CIN; c++) {
        wk0[c] = __ldg(&w1[(h * CIN + c) * 3 + 0]);
        wk1[c] = __ldg(&w1[(h * CIN + c) * 3 + 1]);
        wk2[c] = __ldg(&w1[(h * CIN + c) * 3 + 2]);
    }
    const float bias = __ldg(&b1[h]);
    const float sc = __fmul_rn(__ldg(&g1[h]), __frsqrt_rn(__fadd_rn(__ldg(&v1[h]), 1e-5f)));
    const float sh = __fsub_rn(__ldg(&be1[h]), __fmul_rn(__ldg(&m1[h]), sc));

    const float* xb = x + (size_t)b * CIN * T_;
    float* op = g_u1 + (size_t)tb * (NB * NH) + b * NH + h;

    float A[CIN], Bv[CIN], Cv[CIN];

#define LOADCOL(D, tt) do { int _t = (tt); bool _ok = ((unsigned)_t < (unsigned)T_); \
    _Pragma("unroll") for (int c = 0; c < CIN; c++) \
        D[c] = _ok ? __ldg(xb + (size_t)c * T_ + _t) : 0.0f; } while (0)

#define EMIT(P, Q, R, i) do { float acc = 0.0f; \
    _Pragma("unroll") for (int c = 0; c < CIN; c++) { \
        acc = __fmaf_rn(wk0[c], P[c], acc); \
        acc = __fmaf_rn(wk1[c], Q[c], acc); \
        acc = __fmaf_rn(wk2[c], R[c], acc); } \
    float u = __fadd_rn(__fmul_rn(__fadd_rn(acc, bias), sc), sh); \
    op[(size_t)(i) * (NB * NH)] = u; } while (0)

    LOADCOL(A,  tb - 1);
    LOADCOL(Bv, tb);
#pragma unroll 1
    for (int i = 0; i < 126; i += 3) {               // 3-phase register window
        LOADCOL(Cv, tb + i + 1); EMIT(A,  Bv, Cv, i);
        LOADCOL(A,  tb + i + 2); EMIT(Bv, Cv, A,  i + 1);
        LOADCOL(Bv, tb + i + 3); EMIT(Cv, A,  Bv, i + 2);
    }
    LOADCOL(Cv, tb + 127); EMIT(A,  Bv, Cv, 126);
    LOADCOL(A,  tb + 128); EMIT(Bv, Cv, A,  127);
#undef LOADCOL
#undef EMIT
}

// ---------------------------------------------------------------------------
// K2: LIF layer 1. Warp = one batch b, lane = channel h. 12-cyc/step chain.
// Emits spike bitmasks via ballot. Double-buffered 32-step chunks.
// Exact restructure of: v += (x - v)/2; spike = v>=1; v *= (1-spike).
// ---------------------------------------------------------------------------
__global__ void __launch_bounds__(32) k2_lif1()
{
    const int b    = blockIdx.x;              // 64 blocks x 32 threads
    const int lane = threadIdx.x;
    const float* up = g_u1 + b * NH + lane;
    unsigned* mp = g_mask + (size_t)b * T_;

    float bufA[32], bufB[32];
    float vm = 0.0f;                          // pre-reset membrane of prev step
    bool  sp = false;                         // spike at prev step

#define LOADCH(D, ch) do { size_t _o = (size_t)(ch) * 32 * (NB * NH); \
    _Pragma("unroll") for (int i = 0; i < 32; i++) \
        D[i] = up[_o + (size_t)i * (NB * NH)]; } while (0)

#define STEPS(D, ch) do { unsigned mymask = 0; \
    _Pragma("unroll") for (int i = 0; i < 32; i++) { \
        float xx  = D[i]; \
        float dns = __fsub_rn(xx, vm); \
        float dd  = sp ? xx   : dns; \
        float vp  = sp ? 0.0f : vm; \
        vm = __fmaf_rn(dd, 0.5f, vp); \
        sp = (vm >= 1.0f); \
        unsigned bal = __ballot_sync(0xffffffffu, sp); \
        if (lane == i) mymask = bal; } \
    mp[(ch) * 32 + lane] = mymask; } while (0)

    LOADCH(bufA, 0);
#pragma unroll 1
    for (int c0 = 0; c0 < 512; c0 += 2) {
        LOADCH(bufB, c0 + 1);
        STEPS(bufA, c0);
        LOADCH(bufA, c0 + 2);                 // over-reads into pad on last iter
        STEPS(bufB, c0 + 1);
    }
#undef LOADCH
#undef STEPS
}

// ---------------------------------------------------------------------------
// K3: conv2 + BN2 from spike bitmasks (sparse weight-gather) -> g_u2.
// Warp handles one timestep (mask uniform across warp -> no divergence),
// lane handles 2 output channels (float2). Sum of selected weights is
// bit-exact vs dense in-order accumulation (skipped terms are exact zeros).
// ---------------------------------------------------------------------------
__global__ void __launch_bounds__(256) k3_conv2(
    const float* __restrict__ w2, const float* __restrict__ b2,
    const float* __restrict__ g2, const float* __restrict__ be2,
    const float* __restrict__ m2, const float* __restrict__ v2)
{
    __shared__ float    ws[3 * NH * NE];      // ws[(k*NH + c)*NE + e]
    __shared__ unsigned ms[512 + 2];
    const int tid = threadIdx.x;
    const int b   = blockIdx.y;
    const int t0  = blockIdx.x * 512;

    for (int i = tid; i < 3 * NH * NE; i += 256) {
        int k = i >> 11; int c = (i >> 6) & (NH - 1); int e = i & (NE - 1);
        ws[i] = w2[((size_t)e * NH + c) * 3 + k];
    }
    for (int i = tid; i < 514; i += 256) {
        int g = t0 - 1 + i;
        ms[i] = ((unsigned)g < (unsigned)T_) ? g_mask[(size_t)b * T_ + g] : 0u;
    }
    __syncthreads();

    const int warp = tid >> 5, lane = tid & 31;
    const int e0 = lane * 2;
    const float sc0 = __fmul_rn(g2[e0],   __frsqrt_rn(__fadd_rn(v2[e0],   1e-5f)));
    const float sh0 = __fsub_rn(be2[e0],   __fmul_rn(m2[e0],   sc0));
    const float bb0 = b2[e0];
    const float sc1 = __fmul_rn(g2[e0+1], __frsqrt_rn(__fadd_rn(v2[e0+1], 1e-5f)));
    const float sh1 = __fsub_rn(be2[e0+1], __fmul_rn(m2[e0+1], sc1));
    const float bb1 = b2[e0+1];

    for (int i = warp; i < 512; i += 8) {
        unsigned mk0 = ms[i], mk1 = ms[i + 1], mk2 = ms[i + 2];
        float a0 = 0.0f, a1 = 0.0f;
        unsigned r;
        r = mk0;
        while (r) { int c = __ffs(r) - 1; r &= r - 1;
            const float2 w = *(const float2*)&ws[(0 * NH + c) * NE + e0];
            a0 = __fadd_rn(a0, w.x); a1 = __fadd_rn(a1, w.y); }
        r = mk1;
        while (r) { int c = __ffs(r) - 1; r &= r - 1;
            const float2 w = *(const float2*)&ws[(1 * NH + c) * NE + e0];
            a0 = __fadd_rn(a0, w.x); a1 = __fadd_rn(a1, w.y); }
        r = mk2;
        while (r) { int c = __ffs(r) - 1; r &= r - 1;
            const float2 w = *(const float2*)&ws[(2 * NH + c) * NE + e0];
            a0 = __fadd_rn(a0, w.x); a1 = __fadd_rn(a1, w.y); }

        float u0 = __fadd_rn(__fmul_rn(__fadd_rn(a0, bb0), sc0), sh0);
        float u1 = __fadd_rn(__fmul_rn(__fadd_rn(a1, bb1), sc1), sh1);
        *(float2*)&g_u2[(size_t)(t0 + i) * (NB * NE) + b * NE + e0] = make_float2(u0, u1);
    }
}

// ---------------------------------------------------------------------------
// K4: LIF layer 2 -> out[B,E,T]. Coalesced time-major reads; spikes buffered
// 32 steps in registers, written as 8x STG.128 per lane (contiguous 128B runs
// per channel row -> no sector write amplification).
// ---------------------------------------------------------------------------
__global__ void __launch_bounds__(32) k4_lif2(float* __restrict__ out)
{
    const int W    = blockIdx.x;              // 128 blocks x 32 threads
    const int lane = threadIdx.x;
    const int col  = W * 32 + lane;           // = b*64 + e
    const float* up = g_u2 + col;
    float* op = out + (size_t)col * T_;

    float bufA[32], bufB[32], ob[32];
    float vm = 0.0f; bool sp = false;

#define LOADCH(D, ch) do { size_t _o = (size_t)(ch) * 32 * (NB * NE); \
    _Pragma("unroll") for (int i = 0; i < 32; i++) \
        D[i] = up[_o + (size_t)i * (NB * NE)]; } while (0)

#define STEPS(D, ch) do { \
    _Pragma("unroll") for (int i = 0; i < 32; i++) { \
        float xx  = D[i]; \
        float dns = __fsub_rn(xx, vm); \
        float dd  = sp ? xx   : dns; \
        float vp  = sp ? 0.0f : vm; \
        vm = __fmaf_rn(dd, 0.5f, vp); \
        sp = (vm >= 1.0f); \
        ob[i] = sp ? 1.0f : 0.0f; } \
    _Pragma("unroll") for (int j = 0; j < 8; j++) { \
        float4 v4 = make_float4(ob[4*j], ob[4*j+1], ob[4*j+2], ob[4*j+3]); \
        *(float4*)(op + (size_t)(ch) * 32 + 4 * j) = v4; } } while (0)

    LOADCH(bufA, 0);
#pragma unroll 1
    for (int c0 = 0; c0 < 512; c0 += 2) {
        LOADCH(bufB, c0 + 1);
        STEPS(bufA, c0);
        LOADCH(bufA, c0 + 2);                 // over-reads into pad on last iter
        STEPS(bufB, c0 + 1);
    }
#undef LOADCH
#undef STEPS
}

// ---------------------------------------------------------------------------
extern "C" void kernel_launch(void* const* d_in, const int* in_sizes, int n_in,
                              void* d_out, int out_size)
{
    const float* x   = (const float*)d_in[0];
    const float* w1  = (const float*)d_in[1];
    const float* b1  = (const float*)d_in[2];
    const float* g1  = (const float*)d_in[3];
    const float* be1 = (const float*)d_in[4];
    const float* m1  = (const float*)d_in[5];
    const float* v1  = (const float*)d_in[6];
    const float* w2  = (const float*)d_in[7];
    const float* b2  = (const float*)d_in[8];
    const float* g2  = (const float*)d_in[9];
    const float* be2 = (const float*)d_in[10];
    const float* m2  = (const float*)d_in[11];
    const float* v2  = (const float*)d_in[12];
    float* out = (float*)d_out;

    k1_conv1<<<dim3(16, 64), 256>>>(x, w1, b1, g1, be1, m1, v1);
    k2_lif1 <<<64, 32>>>();
    k3_conv2<<<dim3(32, 64), 256>>>(w2, b2, g2, be2, m2, v2);
    k4_lif2 <<<128, 32>>>(out);
}

// round 2
// speedup vs baseline: 11.1663x; 11.1663x over previous
#include <cuda_runtime.h>

#define T_   16384
#define NB   64
#define CIN  8
#define NH   32
#define NE   64
#define L_   512          // timesteps per segment
#define W_   64           // warm-up steps (v_in influence decays 2^-64 -> bit-exact)
#define NSEG 32           // T_/L_
#define XS   584          // kA smem cols: L+W+2 = 578 (+ prefetch pad)

// Spike bitmasks (device globals; allocation-free contract).
__device__ unsigned g_mask[(size_t)NB * T_];  // layer-1: bit h of word (b,t)
__device__ unsigned g_me[(size_t)NB * T_];    // layer-2 even channels: bit j = e=2j
__device__ unsigned g_mo[(size_t)NB * T_];    // layer-2 odd  channels: bit j = e=2j+1

// ---------------------------------------------------------------------------
// kA: conv1(k=3,same) + BN1 + LIF1 -> g_mask.  One warp per (b, segment);
// lane = channel h.  x tile staged in smem column-major-by-t (float4 pairs).
// 4-phase register window; LIF restructured bit-exactly (tau=2 -> *0.5 exact).
// ---------------------------------------------------------------------------
__global__ void __launch_bounds__(32) kA(
    const float* __restrict__ x,  const float* __restrict__ w1,
    const float* __restrict__ b1, const float* __restrict__ g1,
    const float* __restrict__ be1,const float* __restrict__ m1,
    const float* __restrict__ v1)
{
    __shared__ float xs[XS * CIN];
    const int lane = threadIdx.x;
    const int seg  = blockIdx.x;
    const int b    = blockIdx.y;
    const int t0   = seg * L_;

    float wk0[8], wk1[8], wk2[8];
#pragma unroll
    for (int c = 0; c < 8; c++) {
        wk0[c] = __ldg(&w1[(lane * CIN + c) * 3 + 0]);
        wk1[c] = __ldg(&w1[(lane * CIN + c) * 3 + 1]);
        wk2[c] = __ldg(&w1[(lane * CIN + c) * 3 + 2]);
    }
    const float bias = __ldg(&b1[lane]);
    const float sc = __fmul_rn(__ldg(&g1[lane]), __frsqrt_rn(__fadd_rn(__ldg(&v1[lane]), 1e-5f)));
    const float sh = __fsub_rn(__ldg(&be1[lane]), __fmul_rn(__ldg(&m1[lane]), sc));

    // Stage x[b, :, t0-W-1 .. t0+L+pad] transposed: xs[j*8+c], zero-filled OOR.
    const float* xb = x + (size_t)b * CIN * T_;
    for (int j = lane; j < XS; j += 32) {
        int t = t0 - W_ - 1 + j;
        bool ok = ((unsigned)t < (unsigned)T_);
#pragma unroll
        for (int c = 0; c < 8; c++)
            xs[j * 8 + c] = ok ? __ldg(xb + (size_t)c * T_ + t) : 0.0f;
    }
    __syncwarp();

    float vm = 0.0f;                 // pre-reset membrane of previous step
    bool  sp = false;                // spike at previous step
    unsigned mym = 0;

    const int s0 = (seg == 0) ? W_ : 0;   // segment 0: true v=0 start, no warm-up
    float4 Aa = *(const float4*)&xs[(s0    ) * 8], Ab = *(const float4*)&xs[(s0    ) * 8 + 4];
    float4 Ba = *(const float4*)&xs[(s0 + 1) * 8], Bb = *(const float4*)&xs[(s0 + 1) * 8 + 4];
    float4 Ca = *(const float4*)&xs[(s0 + 2) * 8], Cb = *(const float4*)&xs[(s0 + 2) * 8 + 4];
    float4 Da, Db;

#define KA_STEP(Pa,Pb,Qa,Qb,Ra,Rb,La,Lb,JL,DOEMIT,SI) { \
    La = *(const float4*)&xs[(JL) * 8]; \
    Lb = *(const float4*)&xs[(JL) * 8 + 4]; \
    float acc = 0.0f; \
    acc=__fmaf_rn(wk0[0],Pa.x,acc); acc=__fmaf_rn(wk1[0],Qa.x,acc); acc=__fmaf_rn(wk2[0],Ra.x,acc); \
    acc=__fmaf_rn(wk0[1],Pa.y,acc); acc=__fmaf_rn(wk1[1],Qa.y,acc); acc=__fmaf_rn(wk2[1],Ra.y,acc); \
    acc=__fmaf_rn(wk0[2],Pa.z,acc); acc=__fmaf_rn(wk1[2],Qa.z,acc); acc=__fmaf_rn(wk2[2],Ra.z,acc); \
    acc=__fmaf_rn(wk0[3],Pa.w,acc); acc=__fmaf_rn(wk1[3],Qa.w,acc); acc=__fmaf_rn(wk2[3],Ra.w,acc); \
    acc=__fmaf_rn(wk0[4],Pb.x,acc); acc=__fmaf_rn(wk1[4],Qb.x,acc); acc=__fmaf_rn(wk2[4],Rb.x,acc); \
    acc=__fmaf_rn(wk0[5],Pb.y,acc); acc=__fmaf_rn(wk1[5],Qb.y,acc); acc=__fmaf_rn(wk2[5],Rb.y,acc); \
    acc=__fmaf_rn(wk0[6],Pb.z,acc); acc=__fmaf_rn(wk1[6],Qb.z,acc); acc=__fmaf_rn(wk2[6],Rb.z,acc); \
    acc=__fmaf_rn(wk0[7],Pb.w,acc); acc=__fmaf_rn(wk1[7],Qb.w,acc); acc=__fmaf_rn(wk2[7],Rb.w,acc); \
    float u   = __fadd_rn(__fmul_rn(__fadd_rn(acc, bias), sc), sh); \
    float dns = __fsub_rn(u, vm); \
    float dd  = sp ? u    : dns; \
    float vp  = sp ? 0.0f : vm; \
    vm = __fmaf_rn(dd, 0.5f, vp); \
    sp = (vm >= 1.0f); \
    if (DOEMIT) { unsigned bal = __ballot_sync(0xffffffffu, sp); \
                  if (lane == (SI)) mym = bal; } }

    if (seg != 0) {
#pragma unroll 1
        for (int s = 0; s < W_; s += 4) {
            KA_STEP(Aa,Ab,Ba,Bb,Ca,Cb,Da,Db, s + 3, 0, 0)
            KA_STEP(Ba,Bb,Ca,Cb,Da,Db,Aa,Ab, s + 4, 0, 0)
            KA_STEP(Ca,Cb,Da,Db,Aa,Ab,Ba,Bb, s + 5, 0, 0)
            KA_STEP(Da,Db,Aa,Ab,Ba,Bb,Ca,Cb, s + 6, 0, 0)
        }
    }
    unsigned* mp = g_mask + (size_t)b * T_ + t0;
#pragma unroll 1
    for (int g = 0; g < 16; g++) {
        const int sb = W_ + g * 32;
#pragma unroll 1
        for (int si = 0; si < 32; si += 4) {
            KA_STEP(Aa,Ab,Ba,Bb,Ca,Cb,Da,Db, sb + si + 3, 1, si + 0)
            KA_STEP(Ba,Bb,Ca,Cb,Da,Db,Aa,Ab, sb + si + 4, 1, si + 1)
            KA_STEP(Ca,Cb,Da,Db,Aa,Ab,Ba,Bb, sb + si + 5, 1, si + 2)
            KA_STEP(Da,Db,Aa,Ab,Ba,Bb,Ca,Cb, sb + si + 6, 1, si + 3)
        }
        mp[g * 32 + lane] = mym;
    }
#undef KA_STEP
}

// ---------------------------------------------------------------------------
// kB: sparse conv2 + BN2 + LIF2 -> even/odd bitmasks.  Block = 4 warps = 4
// consecutive segments of one batch, sharing the weight table in smem.
// Rolling 3-accumulator scheme preserves R1's bit-exact summation order:
// for y[t]: bits of m(t-1) w/ tap0 asc, then m(t) tap1, then m(t+1) tap2.
// Lane covers e0=2*lane and e0+1.
// ---------------------------------------------------------------------------
#define MSZ (4 * L_ + W_ + 8)   // 2120

__global__ void __launch_bounds__(128) kB(
    const float* __restrict__ w2, const float* __restrict__ b2,
    const float* __restrict__ g2, const float* __restrict__ be2,
    const float* __restrict__ m2, const float* __restrict__ v2)
{
    __shared__ float4   ws4[NH * 32];   // [c][lane] = {k0e0,k0e1,k1e0,k1e1}
    __shared__ float2   ws2[NH * 32];   // [c][lane] = {k2e0,k2e1}
    __shared__ unsigned ms[MSZ];

    const int tid  = threadIdx.x;
    const int lane = tid & 31;
    const int w    = tid >> 5;
    const int b    = blockIdx.y;
    const int tblk = blockIdx.x * (4 * L_);

    for (int i = tid; i < NH * 32; i += 128) {
        int c = i >> 5, l = i & 31, e0 = l * 2;
        ws4[i] = make_float4(w2[(e0 * NH + c) * 3 + 0], w2[((e0 + 1) * NH + c) * 3 + 0],
                             w2[(e0 * NH + c) * 3 + 1], w2[((e0 + 1) * NH + c) * 3 + 1]);
        ws2[i] = make_float2(w2[(e0 * NH + c) * 3 + 2], w2[((e0 + 1) * NH + c) * 3 + 2]);
    }
    for (int j = tid; j < MSZ; j += 128) {
        int t = tblk - W_ - 1 + j;
        ms[j] = ((unsigned)t < (unsigned)T_) ? g_mask[(size_t)b * T_ + t] : 0u;
    }
    __syncthreads();

    const int seg  = blockIdx.x * 4 + w;
    const int t0   = seg * L_;
    const int base = w * L_;            // this warp's offset into ms
    const int e0   = lane * 2;

    const float sc0 = __fmul_rn(g2[e0],     __frsqrt_rn(__fadd_rn(v2[e0],     1e-5f)));
    const float sh0 = __fsub_rn(be2[e0],     __fmul_rn(m2[e0],     sc0));
    const float bb0 = b2[e0];
    const float sc1 = __fmul_rn(g2[e0 + 1], __frsqrt_rn(__fadd_rn(v2[e0 + 1], 1e-5f)));
    const float sh1 = __fsub_rn(be2[e0 + 1], __fmul_rn(m2[e0 + 1], sc1));
    const float bb1 = b2[e0 + 1];

    float aA0 = 0.f, aA1 = 0.f, aB0 = 0.f, aB1 = 0.f, aC0 = 0.f, aC1 = 0.f;
    float vm0 = 0.f, vm1 = 0.f;
    bool  sp0 = false, sp1 = false;
    unsigned mme = 0, mmo = 0;

    const int s0 = (seg == 0) ? W_ : 0;

    // Prime: word(s0) contributes tap0 to y(t(s0)); word(s0+1) tap1->A, tap0->B.
    { unsigned r = ms[base + s0];
      while (r) { int c = __ffs(r) - 1; r &= r - 1;
          float4 q = ws4[(c << 5) + lane];
          aA0 = __fadd_rn(aA0, q.x); aA1 = __fadd_rn(aA1, q.y); } }
    { unsigned r = ms[base + s0 + 1];
      while (r) { int c = __ffs(r) - 1; r &= r - 1;
          float4 q = ws4[(c << 5) + lane];
          aA0 = __fadd_rn(aA0, q.z); aA1 = __fadd_rn(aA1, q.w);
          aB0 = __fadd_rn(aB0, q.x); aB1 = __fadd_rn(aB1, q.y); } }

#define KB_STEP(JW, DOEMIT, SI) { \
    unsigned r = ms[JW]; \
    while (r) { int c = __ffs(r) - 1; r &= r - 1; \
        float4 q = ws4[(c << 5) + lane]; \
        float2 p = ws2[(c << 5) + lane]; \
        aA0 = __fadd_rn(aA0, p.x); aA1 = __fadd_rn(aA1, p.y); \
        aB0 = __fadd_rn(aB0, q.z); aB1 = __fadd_rn(aB1, q.w); \
        aC0 = __fadd_rn(aC0, q.x); aC1 = __fadd_rn(aC1, q.y); } \
    float u0 = __fadd_rn(__fmul_rn(__fadd_rn(aA0, bb0), sc0), sh0); \
    float u1 = __fadd_rn(__fmul_rn(__fadd_rn(aA1, bb1), sc1), sh1); \
    float d0 = __fsub_rn(u0, vm0); float dd0 = sp0 ? u0 : d0; float vp0 = sp0 ? 0.0f : vm0; \
    vm0 = __fmaf_rn(dd0, 0.5f, vp0); sp0 = (vm0 >= 1.0f); \
    float d1 = __fsub_rn(u1, vm1); float dd1 = sp1 ? u1 : d1; float vp1 = sp1 ? 0.0f : vm1; \
    vm1 = __fmaf_rn(dd1, 0.5f, vp1); sp1 = (vm1 >= 1.0f); \
    aA0 = aB0; aA1 = aB1; aB0 = aC0; aB1 = aC1; aC0 = 0.0f; aC1 = 0.0f; \
    if (DOEMIT) { unsigned be_ = __ballot_sync(0xffffffffu, sp0); \
                  unsigned bo_ = __ballot_sync(0xffffffffu, sp1); \
                  if (lane == (SI)) { mme = be_; mmo = bo_; } } }

    if (seg != 0) {
#pragma unroll 1
        for (int s = 0; s < W_; s++) KB_STEP(base + s + 2, 0, 0)
    }
    unsigned* mpE = g_me + (size_t)b * T_ + t0;
    unsigned* mpO = g_mo + (size_t)b * T_ + t0;
#pragma unroll 1
    for (int g = 0; g < 16; g++) {
        const int jb = base + W_ + g * 32 + 2;
#pragma unroll 1
        for (int si = 0; si < 32; si++) KB_STEP(jb + si, 1, si)
        mpE[g * 32 + lane] = mme;
        mpO[g * 32 + lane] = mmo;
    }
#undef KB_STEP
}

// ---------------------------------------------------------------------------
// kC: expand bitmasks -> out[B,E,T] float 0/1.  Warp covers 2048 consecutive
// t of one (b,e) row: fully coalesced uint4 reads + float4 writes.
// ---------------------------------------------------------------------------
__global__ void __launch_bounds__(256) kC(float* __restrict__ out)
{
    const int lane = threadIdx.x & 31;
    const int gw   = blockIdx.x * 8 + (threadIdx.x >> 5);  // 0..32767
    const int row  = gw >> 3;                              // b*64 + e
    const int tc   = (gw & 7) * 2048;
    const int b    = row >> 6;
    const int e    = row & 63;
    const int bit  = e >> 1;

    const unsigned* msrc = ((e & 1) ? g_mo : g_me) + (size_t)b * T_ + tc;
    float* op = out + (size_t)row * T_ + tc;

#pragma unroll 4
    for (int i = 0; i < 16; i++) {
        uint4 m = *(const uint4*)&msrc[i * 128 + lane * 4];
        float4 v;
        v.x = ((m.x >> bit) & 1u) ? 1.0f : 0.0f;
        v.y = ((m.y >> bit) & 1u) ? 1.0f : 0.0f;
        v.z = ((m.z >> bit) & 1u) ? 1.0f : 0.0f;
        v.w = ((m.w >> bit) & 1u) ? 1.0f : 0.0f;
        *(float4*)&op[i * 128 + lane * 4] = v;
    }
}

// ---------------------------------------------------------------------------
extern "C" void kernel_launch(void* const* d_in, const int* in_sizes, int n_in,
                              void* d_out, int out_size)
{
    const float* x   = (const float*)d_in[0];
    const float* w1  = (const float*)d_in[1];
    const float* b1  = (const float*)d_in[2];
    const float* g1  = (const float*)d_in[3];
    const float* be1 = (const float*)d_in[4];
    const float* m1  = (const float*)d_in[5];
    const float* v1  = (const float*)d_in[6];
    const float* w2  = (const float*)d_in[7];
    const float* b2  = (const float*)d_in[8];
    const float* g2  = (const float*)d_in[9];
    const float* be2 = (const float*)d_in[10];
    const float* m2  = (const float*)d_in[11];
    const float* v2  = (const float*)d_in[12];
    float* out = (float*)d_out;

    kA<<<dim3(NSEG, NB), 32>>>(x, w1, b1, g1, be1, m1, v1);
    kB<<<dim3(NSEG / 4, NB), 128>>>(w2, b2, g2, be2, m2, v2);
    kC<<<4096, 256>>>(out);
}